// round 8
// baseline (speedup 1.0000x reference)
#include <cuda_runtime.h>
#include <cuda_bf16.h>
#include <stdint.h>

// Problem constants
#define Bb_  4
#define T_   128
#define V_   50257
#define LSRC 512
#define D_   512
#define MROWS 512              // B*T

// GEMM tiling: 256x256 CTA tile, BK=32, 512 threads, split-K 36
#define BM 256
#define BN 256
#define BK 32
#define NT 512
#define KT2 1571               // ceil(50257/32)
#define KSL 36                 // grid: 2 n-blocks * 2 m-blocks * 36 = 144 CTAs
#define TPS 44                 // ceil(1571/36)

#define WSTAGE_F (32*264)                  // floats per fp32 W stage
#define SAST (256*40)                      // bf16 elems per sA buffer
#define SBST (32*264)                      // bf16 elems per sB buffer
#define OFF_SA (3*WSTAGE_F*4)              // 101376
#define OFF_SB (OFF_SA + 2*SAST*2)         // 101376 + 40960 = 142336
#define SMEM_BYTES (OFF_SB + 2*SBST*2)     // 142336 + 33792 = 176128

__device__ float g_Upart[KSL][MROWS * D_];   // split-K partials (every elem written)
__device__ float g_scal[8];                   // 0:cov 1:nll 2:valid 3:cos

__device__ __forceinline__ float warp_sum(float v) {
    #pragma unroll
    for (int o = 16; o > 0; o >>= 1) v += __shfl_xor_sync(0xffffffffu, v, o);
    return v;
}
__device__ __forceinline__ void cp_async16(void* dst, const void* src) {
    uint32_t d = (uint32_t)__cvta_generic_to_shared(dst);
    asm volatile("cp.async.cg.shared.global [%0], [%1], 16;\n" :: "r"(d), "l"(src));
}
__device__ __forceinline__ void cp_commit() {
    asm volatile("cp.async.commit_group;\n" ::: "memory");
}
__device__ __forceinline__ void cp_wait1() {
    asm volatile("cp.async.wait_group 1;\n" ::: "memory");
}
__device__ __forceinline__ void ldmatrix_x4(unsigned* r, uint32_t addr) {
    asm volatile("ldmatrix.sync.aligned.m8n8.x4.shared.b16 {%0,%1,%2,%3}, [%4];"
                 : "=r"(r[0]), "=r"(r[1]), "=r"(r[2]), "=r"(r[3]) : "r"(addr));
}
__device__ __forceinline__ void ldmatrix_x4_trans(unsigned* r, uint32_t addr) {
    asm volatile("ldmatrix.sync.aligned.m8n8.x4.trans.shared.b16 {%0,%1,%2,%3}, [%4];"
                 : "=r"(r[0]), "=r"(r[1]), "=r"(r[2]), "=r"(r[3]) : "r"(addr));
}
__device__ __forceinline__ void mma16816(float* c, const unsigned* a, unsigned b0, unsigned b1) {
    asm volatile(
        "mma.sync.aligned.m16n8k16.row.col.f32.bf16.bf16.f32 "
        "{%0,%1,%2,%3}, {%4,%5,%6,%7}, {%8,%9}, {%0,%1,%2,%3};\n"
        : "+f"(c[0]), "+f"(c[1]), "+f"(c[2]), "+f"(c[3])
        : "r"(a[0]), "r"(a[1]), "r"(a[2]), "r"(a[3]), "r"(b0), "r"(b1));
}
__device__ __forceinline__ unsigned packbf(float lo, float hi) {
    __nv_bfloat162 h = __floats2bfloat162_rn(lo, hi);
    return *reinterpret_cast<unsigned*>(&h);
}

// ---------------- zero scalars ----------------
__global__ void zero_kernel() {
    if (threadIdx.x < 8) g_scal[threadIdx.x] = 0.f;
}

// ------- fused split-K bf16 GEMM: Upart[z] = exp(X) @ W (k-slice z), pipelined -------
__global__ __launch_bounds__(NT, 1) void gemm_fused(
    const float* __restrict__ X, const float* __restrict__ W)
{
    extern __shared__ char smem[];
    float* wbuf = (float*)smem;                                  // [3][32*264] fp32
    __nv_bfloat16* sA = (__nv_bfloat16*)(smem + OFF_SA);         // [2][256][40]
    __nv_bfloat16* sB = (__nv_bfloat16*)(smem + OFF_SB);         // [2][32][264] k-major

    const int bn = blockIdx.x * BN;
    const int bm = blockIdx.y * BM;
    const int t0 = blockIdx.z * TPS;
    const int t1 = min(KT2, t0 + TPS);
    const int tid = threadIdx.x;
    const int warp = tid >> 5, lane = tid & 31;
    const int wm = (warp & 3) * 64;      // 4 m-warps (64 rows each)
    const int wn = (warp >> 2) * 64;     // 4 n-warps (64 cols each)
    const int g = lane >> 2, q = lane & 3;
    const int lm16 = lane & 15, lkh = (lane >> 4) * 8;
    const int bmm = lane >> 3, br = lane & 7;

    const uint32_t sAu = (uint32_t)__cvta_generic_to_shared(sA);
    const uint32_t sBu = (uint32_t)__cvta_generic_to_shared(sB);

    // X mapping: 2 threads per row, 16 consecutive k each
    const int xrow = tid >> 1;
    const int xcol = (tid & 1) * 16;

    float acc[4][8][4];
    #pragma unroll
    for (int i = 0; i < 4; i++)
        #pragma unroll
        for (int j = 0; j < 8; j++)
            #pragma unroll
            for (int k = 0; k < 4; k++) acc[i][j][k] = 0.f;

    float xr[16];
    unsigned xh[8];

    auto issueW = [&](int kt) {
        if (kt < t1) {
            const int k0 = kt * BK;
            float* dst = wbuf + (kt % 3) * WSTAGE_F;
            if (k0 + BK <= V_) {
                #pragma unroll
                for (int i = 0; i < 4; ++i) {
                    int c = tid + i * NT;
                    int k = c >> 6, n4 = (c & 63) * 4;
                    cp_async16(dst + k * 264 + n4,
                               W + (size_t)(k0 + k) * D_ + bn + n4);
                }
            } else {
                #pragma unroll
                for (int i = 0; i < 4; ++i) {
                    int c = tid + i * NT;
                    int k = c >> 6, n4 = (c & 63) * 4;
                    float4 v = make_float4(0.f, 0.f, 0.f, 0.f);
                    if (k0 + k < V_)
                        v = *(const float4*)(W + (size_t)(k0 + k) * D_ + bn + n4);
                    *(float4*)(dst + k * 264 + n4) = v;
                }
            }
        }
        cp_commit();
    };
    auto ldgX = [&](int kt) {
        if (kt >= t1) return;
        const int k0 = kt * BK;
        const float* p = X + (size_t)(bm + xrow) * V_ + k0 + xcol;
        if (k0 + BK <= V_) {
            #pragma unroll
            for (int j = 0; j < 16; ++j) xr[j] = __ldg(p + j);
        } else {
            #pragma unroll
            for (int j = 0; j < 16; ++j)
                xr[j] = (k0 + xcol + j < V_) ? __ldg(p + j) : 0.f;
        }
    };
    auto expX = [&]() {
        #pragma unroll
        for (int j = 0; j < 8; ++j)
            xh[j] = packbf(__expf(xr[2 * j]), __expf(xr[2 * j + 1]));
    };
    auto convX = [&](int kt) {   // xh -> sA[kt&1]
        __nv_bfloat16* dstA = sA + (kt & 1) * SAST;
        *(uint4*)&dstA[xrow * 40 + xcol]     = *(uint4*)&xh[0];
        *(uint4*)&dstA[xrow * 40 + xcol + 8] = *(uint4*)&xh[4];
    };
    auto convW = [&](int kt) {   // own-copied wbuf stage -> sB[kt&1]
        const float* src = wbuf + (kt % 3) * WSTAGE_F;
        __nv_bfloat16* dstB = sB + (kt & 1) * SBST;
        #pragma unroll
        for (int i = 0; i < 4; ++i) {
            int c = tid + i * NT;
            int k = c >> 6, n4 = (c & 63) * 4;
            float4 v = *(const float4*)(src + k * 264 + n4);
            uint2 u = make_uint2(packbf(v.x, v.y), packbf(v.z, v.w));
            *(uint2*)&dstB[k * 264 + n4] = u;
        }
    };

    // ---- prologue: fill buffers for tile t0, prefetch t0+1 ----
    issueW(t0);
    issueW(t0 + 1);
    ldgX(t0);
    cp_wait1();             // own group t0 complete
    expX();
    convX(t0);
    convW(t0);
    ldgX(t0 + 1);
    issueW(t0 + 2);
    __syncthreads();        // buffers (t0&1) visible to all

    for (int kt = t0; kt < t1; ++kt) {
        const int cur = kt & 1;
        const bool hn = (kt + 1 < t1);

        if (hn) expX();     // exp of X(kt+1); LDG latency covered by prev iteration

        // ---- mma on buffers[cur] ----
        const uint32_t sAc = sAu + (uint32_t)(cur * SAST * 2);
        const uint32_t sBc = sBu + (uint32_t)(cur * SBST * 2);
        #pragma unroll
        for (int kk = 0; kk < 2; ++kk) {
            unsigned a0[4][4];
            #pragma unroll
            for (int mf = 0; mf < 4; ++mf) {
                uint32_t addr = sAc +
                    (uint32_t)(((wm + mf * 16 + lm16) * 40 + kk * 16 + lkh) * 2);
                ldmatrix_x4(a0[mf], addr);
            }
            #pragma unroll
            for (int p = 0; p < 4; ++p) {
                unsigned bfr[4];
                int ksrc = kk * 16 + (bmm & 1) * 8 + br;
                int nsrc = wn + p * 16 + (bmm >> 1) * 8;
                ldmatrix_x4_trans(bfr, sBc + (uint32_t)((ksrc * 264 + nsrc) * 2));
                #pragma unroll
                for (int mf = 0; mf < 4; ++mf) {
                    mma16816(acc[mf][2 * p],     a0[mf], bfr[0], bfr[1]);
                    mma16816(acc[mf][2 * p + 1], a0[mf], bfr[2], bfr[3]);
                }
            }
        }

        if (hn) {
            cp_wait1();          // own cp group (kt+1) complete
            convX(kt + 1);       // write buffers[nxt]: safe vs readers via prev barrier
            convW(kt + 1);
            ldgX(kt + 2);
            issueW(kt + 3);
            __syncthreads();     // buffers[nxt] visible for next iteration
        }
    }

    // ---- epilogue: plain stores to this slice's partial buffer ----
    float* up = g_Upart[blockIdx.z];
    #pragma unroll
    for (int mf = 0; mf < 4; ++mf) {
        int r0 = bm + wm + mf * 16 + g;
        #pragma unroll
        for (int nf = 0; nf < 8; ++nf) {
            int c0 = bn + wn + nf * 8 + q * 2;
            *(float2*)&up[r0 * D_ + c0]       = make_float2(acc[mf][nf][0], acc[mf][nf][1]);
            *(float2*)&up[(r0 + 8) * D_ + c0] = make_float2(acc[mf][nf][2], acc[mf][nf][3]);
        }
    }
}

// ---------------- coverage + NLL fused ----------------
__global__ void covnll_kernel(const float* __restrict__ attn,
                              const float* __restrict__ covg,
                              const int* __restrict__ mask,
                              const float* __restrict__ X,
                              const int* __restrict__ trg) {
    if (blockIdx.x < 128) {
        float s = 0.f;
        const int total = Bb_ * LSRC * T_;   // 262144
        for (int idx = blockIdx.x * blockDim.x + threadIdx.x; idx < total;
             idx += 128 * blockDim.x) {
            int t = idx & (T_ - 1);
            int b = idx >> 16;
            if (mask[(b << 7) + t] == 0) s += fminf(attn[idx], covg[idx]);
        }
        s = warp_sum(s);
        __shared__ float sm[8];
        int warp = threadIdx.x >> 5, lane = threadIdx.x & 31;
        if (lane == 0) sm[warp] = s;
        __syncthreads();
        if (threadIdx.x == 0) {
            float tot = 0.f;
            for (int w = 0; w < (int)(blockDim.x >> 5); ++w) tot += sm[w];
            atomicAdd(&g_scal[0], tot);
        }
    } else {
        float s = 0.f, c = 0.f;
        #pragma unroll
        for (int r = 0; r < 2; ++r) {
            int i = threadIdx.x + r * 256;
            int tg = trg[i];
            if (tg != 0) {
                s += logf(X[(size_t)i * V_ + tg]);
                c += 1.f;
            }
        }
        s = warp_sum(s);
        c = warp_sum(c);
        __shared__ float sms[8], smc[8];
        int warp = threadIdx.x >> 5, lane = threadIdx.x & 31;
        if (lane == 0) { sms[warp] = s; smc[warp] = c; }
        __syncthreads();
        if (threadIdx.x == 0) {
            float ts = 0.f, tc = 0.f;
            for (int w = 0; w < 8; ++w) { ts += sms[w]; tc += smc[w]; }
            atomicAdd(&g_scal[1], ts);
            atomicAdd(&g_scal[2], tc);
        }
    }
}

// ------- per-row cosine (OT via diagonal-IPOT collapse) + split-K reduce -------
__global__ void finalize_kernel(const int* __restrict__ trg, const float* __restrict__ W) {
    int i = blockIdx.x;                  // 512 rows
    int tid = threadIdx.x;               // 128 threads, one float4 (d-chunk) each
    int tg = trg[i];
    int d = tid * 4;
    float4 u = make_float4(0.f, 0.f, 0.f, 0.f);
    #pragma unroll
    for (int s = 0; s < KSL; ++s) {
        float4 p = *(const float4*)&g_Upart[s][i * D_ + d];
        u.x += p.x; u.y += p.y; u.z += p.z; u.w += p.w;
    }
    float4 e = *(const float4*)&W[(size_t)tg * D_ + d];
    float sue = u.x * e.x + u.y * e.y + u.z * e.z + u.w * e.w;
    float suu = u.x * u.x + u.y * u.y + u.z * u.z + u.w * u.w;
    float see = e.x * e.x + e.y * e.y + e.z * e.z + e.w * e.w;
    sue = warp_sum(sue); suu = warp_sum(suu); see = warp_sum(see);
    __shared__ float sm[3][4];
    int warp = tid >> 5, lane = tid & 31;
    if (lane == 0) { sm[0][warp] = sue; sm[1][warp] = suu; sm[2][warp] = see; }
    __syncthreads();
    if (tid == 0) {
        float a = sm[0][0] + sm[0][1] + sm[0][2] + sm[0][3];
        float b = sm[1][0] + sm[1][1] + sm[1][2] + sm[1][3];
        float c = sm[2][0] + sm[2][1] + sm[2][2] + sm[2][3];
        atomicAdd(&g_scal[3], a * rsqrtf(b * c));
    }
}

// ---------------- combine ----------------
__global__ void combine_kernel(const int* __restrict__ dec_len, float* __restrict__ out) {
    int ls = dec_len[0] + dec_len[1] + dec_len[2] + dec_len[3];
    float nll = -g_scal[1] / g_scal[2];
    float cov_loss = g_scal[0] / (float)ls;
    float ot = g_scal[3] / (float)MROWS;
    out[0] = nll + 1.0f * cov_loss + 0.1f + ot;
}

extern "C" void kernel_launch(void* const* d_in, const int* in_sizes, int n_in,
                              void* d_out, int out_size) {
    const float* X    = (const float*)d_in[0];
    const float* attn = (const float*)d_in[1];
    const float* covg = (const float*)d_in[2];
    const int*   trg  = (const int*)d_in[3];
    const int*   mask = (const int*)d_in[4];
    const int*   dlen = (const int*)d_in[5];
    const float* W    = (const float*)d_in[6];
    float* out = (float*)d_out;

    cudaFuncSetAttribute(gemm_fused, cudaFuncAttributeMaxDynamicSharedMemorySize,
                         SMEM_BYTES);

    zero_kernel<<<1, 32>>>();
    covnll_kernel<<<129, 256>>>(attn, covg, mask, X, trg);
    {
        dim3 grid(2, 2, KSL);   // n-blocks, m-blocks, k-slices = 144 CTAs
        gemm_fused<<<grid, NT, SMEM_BYTES>>>(X, W);
    }
    finalize_kernel<<<512, 128>>>(trg, W);
    combine_kernel<<<1, 1>>>(dlen, out);
}

// round 11
// speedup vs baseline: 2.6874x; 2.6874x over previous
#include <cuda_runtime.h>
#include <cuda_bf16.h>
#include <stdint.h>

// Problem constants
#define Bb_  4
#define T_   128
#define V_   50257
#define LSRC 512
#define D_   512
#define MROWS 512              // B*T

// GEMM tiling: 128x256 CTA tile, BK=32, 512 threads, split-K 18 (R7 proven shape)
#define BM 128
#define BN 256
#define BK 32
#define NT 512
#define KT2 1571               // ceil(50257/32)
#define KSL 18
#define TPS 88                 // ceil(1571/18)
#define NGEMM 144              // 2 n-blocks * 4 m-blocks * 18 k-slices
#define NCTA 148               // + 4 covnll CTAs = one full wave

#define WSTAGE_F (32*264)                  // floats per fp32 W stage
#define SAST (128*40)                      // bf16 elems per sA buffer
#define SBST (32*264)                      // bf16 elems per sB buffer
#define OFF_SA (3*WSTAGE_F*4)              // 101376
#define OFF_SB (OFF_SA + 2*SAST*2)         // 121856
#define SMEM_BYTES (OFF_SB + 2*SBST*2)     // 155648

__device__ float g_Upart[KSL][MROWS * D_];   // split-K partials (every elem written)
__device__ float g_scal[8];                   // 0:cov 1:nll 2:valid 3:cos (combine resets)

__device__ __forceinline__ float warp_sum(float v) {
    #pragma unroll
    for (int o = 16; o > 0; o >>= 1) v += __shfl_xor_sync(0xffffffffu, v, o);
    return v;
}
__device__ __forceinline__ void cp_async16(void* dst, const void* src) {
    uint32_t d = (uint32_t)__cvta_generic_to_shared(dst);
    asm volatile("cp.async.cg.shared.global [%0], [%1], 16;\n" :: "r"(d), "l"(src));
}
__device__ __forceinline__ void cp_commit() {
    asm volatile("cp.async.commit_group;\n" ::: "memory");
}
__device__ __forceinline__ void cp_wait1() {
    asm volatile("cp.async.wait_group 1;\n" ::: "memory");
}
__device__ __forceinline__ void ldmatrix_x4(unsigned* r, uint32_t addr) {
    asm volatile("ldmatrix.sync.aligned.m8n8.x4.shared.b16 {%0,%1,%2,%3}, [%4];"
                 : "=r"(r[0]), "=r"(r[1]), "=r"(r[2]), "=r"(r[3]) : "r"(addr));
}
__device__ __forceinline__ void ldmatrix_x4_trans(unsigned* r, uint32_t addr) {
    asm volatile("ldmatrix.sync.aligned.m8n8.x4.trans.shared.b16 {%0,%1,%2,%3}, [%4];"
                 : "=r"(r[0]), "=r"(r[1]), "=r"(r[2]), "=r"(r[3]) : "r"(addr));
}
__device__ __forceinline__ void mma16816(float* c, const unsigned* a, unsigned b0, unsigned b1) {
    asm volatile(
        "mma.sync.aligned.m16n8k16.row.col.f32.bf16.bf16.f32 "
        "{%0,%1,%2,%3}, {%4,%5,%6,%7}, {%8,%9}, {%0,%1,%2,%3};\n"
        : "+f"(c[0]), "+f"(c[1]), "+f"(c[2]), "+f"(c[3])
        : "r"(a[0]), "r"(a[1]), "r"(a[2]), "r"(a[3]), "r"(b0), "r"(b1));
}
__device__ __forceinline__ unsigned packbf(float lo, float hi) {
    __nv_bfloat162 h = __floats2bfloat162_rn(lo, hi);
    return *reinterpret_cast<unsigned*>(&h);
}
// exp of a packed pair via bf16x2 MUFU: exp(x) = 2^(x*log2e)
__device__ __forceinline__ unsigned exp_bf16x2(float x0, float x1) {
    const float L2E = 1.4426950408889634f;
    unsigned p = packbf(x0 * L2E, x1 * L2E);
    unsigned r;
    asm("ex2.approx.ftz.bf16x2 %0, %1;" : "=r"(r) : "r"(p));
    return r;
}

// ======= one-wave kernel: 144 GEMM CTAs + 4 coverage/NLL CTAs =======
__global__ __launch_bounds__(NT, 1) void gemm_fused(
    const float* __restrict__ X, const float* __restrict__ W,
    const float* __restrict__ attn, const float* __restrict__ covg,
    const int* __restrict__ mask, const int* __restrict__ trg)
{
    extern __shared__ char smem[];
    const int id = blockIdx.x;
    const int tid = threadIdx.x;

    if (id >= NGEMM) {
        // ---------- coverage (+ NLL on cid 0) CTA; hides under the GEMM wave ----------
        int* smask = (int*)smem;                 // 512 ints
        float* sred = (float*)(smem + 4096);
        const int cid = id - NGEMM;              // 0..3 == batch index
        smask[tid] = mask[tid];
        __syncthreads();
        float s = 0.f;
        const int* mrow = smask + (cid << 7);
        #pragma unroll 4
        for (int i = 0; i < 32; ++i) {
            int e = (cid << 16) + (i * 512 + tid) * 4;   // elem index, b == cid
            float4 a = *(const float4*)(attn + e);
            float4 c = *(const float4*)(covg + e);
            int t = e & 127;
            if (mrow[t]     == 0) s += fminf(a.x, c.x);
            if (mrow[t + 1] == 0) s += fminf(a.y, c.y);
            if (mrow[t + 2] == 0) s += fminf(a.z, c.z);
            if (mrow[t + 3] == 0) s += fminf(a.w, c.w);
        }
        s = warp_sum(s);
        int warp = tid >> 5, lane = tid & 31;
        if (lane == 0) sred[warp] = s;
        __syncthreads();
        if (tid == 0) {
            float tot = 0.f;
            #pragma unroll
            for (int w = 0; w < 16; ++w) tot += sred[w];
            atomicAdd(&g_scal[0], tot);
        }
        if (cid == 0) {
            // NLL: 512 tokens, one per thread
            float sl = 0.f, cv = 0.f;
            int tg = trg[tid];
            if (tg != 0) {
                sl = logf(X[(size_t)tid * V_ + tg]);
                cv = 1.f;
            }
            sl = warp_sum(sl); cv = warp_sum(cv);
            if (lane == 0) { sred[16 + warp] = sl; sred[32 + warp] = cv; }
            __syncthreads();
            if (tid == 0) {
                float ts = 0.f, tc = 0.f;
                #pragma unroll
                for (int w = 0; w < 16; ++w) { ts += sred[16 + w]; tc += sred[32 + w]; }
                atomicAdd(&g_scal[1], ts);
                atomicAdd(&g_scal[2], tc);
            }
        }
        return;
    }

    // ---------- GEMM CTA: Upart[bz] = exp(X) @ W (k-slice bz) ----------
    float* wbuf = (float*)smem;                                  // [3][32*264] fp32
    __nv_bfloat16* sA = (__nv_bfloat16*)(smem + OFF_SA);         // [2][128][40]
    __nv_bfloat16* sB = (__nv_bfloat16*)(smem + OFF_SB);         // [2][32][264] k-major

    const int bz = id >> 3;            // k-slice 0..17
    const int r7 = id & 7;
    const int by = r7 >> 1;            // m-block 0..3
    const int bx = r7 & 1;             // n-block 0..1
    const int bn = bx * BN;
    const int bm = by * BM;
    const int t0 = bz * TPS;
    const int t1 = min(KT2, t0 + TPS);
    const int warp = tid >> 5, lane = tid & 31;
    const int wm = (warp & 3) * 32;      // 4 m-warps
    const int wn = (warp >> 2) * 64;     // 4 n-warps
    const int g = lane >> 2, q = lane & 3;
    const int lm16 = lane & 15, lkh = (lane >> 4) * 8;
    const int bmm = lane >> 3, br = lane & 7;

    const uint32_t sAu = (uint32_t)__cvta_generic_to_shared(sA);
    const uint32_t sBu = (uint32_t)__cvta_generic_to_shared(sB);

    const int xrow = tid >> 2;
    const int xcol = (tid & 3) * 8;

    float acc[2][8][4];
    #pragma unroll
    for (int i = 0; i < 2; i++)
        #pragma unroll
        for (int j = 0; j < 8; j++)
            #pragma unroll
            for (int k = 0; k < 4; k++) acc[i][j][k] = 0.f;

    float xr[8];
    unsigned xh[4];

    auto issueW = [&](int kt) {
        if (kt < t1) {
            const int k0 = kt * BK;
            float* dst = wbuf + (kt % 3) * WSTAGE_F;
            if (k0 + BK <= V_) {
                #pragma unroll
                for (int i = 0; i < 4; ++i) {
                    int c = tid + i * NT;
                    int k = c >> 6, n4 = (c & 63) * 4;
                    cp_async16(dst + k * 264 + n4,
                               W + (size_t)(k0 + k) * D_ + bn + n4);
                }
            } else {
                #pragma unroll
                for (int i = 0; i < 4; ++i) {
                    int c = tid + i * NT;
                    int k = c >> 6, n4 = (c & 63) * 4;
                    float4 v = make_float4(0.f, 0.f, 0.f, 0.f);
                    if (k0 + k < V_)
                        v = *(const float4*)(W + (size_t)(k0 + k) * D_ + bn + n4);
                    *(float4*)(dst + k * 264 + n4) = v;
                }
            }
        }
        cp_commit();
    };
    auto ldgX = [&](int kt) {
        if (kt >= t1) return;
        const int k0 = kt * BK;
        const float* p = X + (size_t)(bm + xrow) * V_ + k0 + xcol;
        if (k0 + BK <= V_) {
            #pragma unroll
            for (int j = 0; j < 8; ++j) xr[j] = __ldg(p + j);
        } else {
            #pragma unroll
            for (int j = 0; j < 8; ++j)
                xr[j] = (k0 + xcol + j < V_) ? __ldg(p + j) : 0.f;
        }
    };
    auto expX = [&]() {
        #pragma unroll
        for (int j = 0; j < 4; ++j)
            xh[j] = exp_bf16x2(xr[2 * j], xr[2 * j + 1]);
    };
    auto convX = [&](int kt) {   // xh -> sA[kt&1]
        __nv_bfloat16* dstA = sA + (kt & 1) * SAST;
        *(uint4*)&dstA[xrow * 40 + xcol] = *(uint4*)xh;
    };
    auto convW = [&](int kt) {   // own-copied wbuf stage -> sB[kt&1]
        const float* src = wbuf + (kt % 3) * WSTAGE_F;
        __nv_bfloat16* dstB = sB + (kt & 1) * SBST;
        #pragma unroll
        for (int i = 0; i < 4; ++i) {
            int c = tid + i * NT;
            int k = c >> 6, n4 = (c & 63) * 4;
            float4 v = *(const float4*)(src + k * 264 + n4);
            uint2 u = make_uint2(packbf(v.x, v.y), packbf(v.z, v.w));
            *(uint2*)&dstB[k * 264 + n4] = u;
        }
    };

    // ---- prologue: fill buffers for tile t0, prefetch t0+1 ----
    issueW(t0);
    issueW(t0 + 1);
    ldgX(t0);
    cp_wait1();             // own group t0 complete
    expX();
    convX(t0);
    convW(t0);
    ldgX(t0 + 1);
    issueW(t0 + 2);
    __syncthreads();        // buffers (t0&1) visible to all

    for (int kt = t0; kt < t1; ++kt) {
        const int cur = kt & 1;
        const bool hn = (kt + 1 < t1);

        if (hn) expX();     // exp of X(kt+1); LDG latency covered by prev iteration

        // ---- mma on buffers[cur] ----
        const uint32_t sAc = sAu + (uint32_t)(cur * SAST * 2);
        const uint32_t sBc = sBu + (uint32_t)(cur * SBST * 2);
        #pragma unroll
        for (int kk = 0; kk < 2; ++kk) {
            unsigned a0[2][4];
            #pragma unroll
            for (int mf = 0; mf < 2; ++mf) {
                uint32_t addr = sAc +
                    (uint32_t)(((wm + mf * 16 + lm16) * 40 + kk * 16 + lkh) * 2);
                ldmatrix_x4(a0[mf], addr);
            }
            #pragma unroll
            for (int p = 0; p < 4; ++p) {
                unsigned bfr[4];
                int ksrc = kk * 16 + (bmm & 1) * 8 + br;
                int nsrc = wn + p * 16 + (bmm >> 1) * 8;
                ldmatrix_x4_trans(bfr, sBc + (uint32_t)((ksrc * 264 + nsrc) * 2));
                #pragma unroll
                for (int mf = 0; mf < 2; ++mf) {
                    mma16816(acc[mf][2 * p],     a0[mf], bfr[0], bfr[1]);
                    mma16816(acc[mf][2 * p + 1], a0[mf], bfr[2], bfr[3]);
                }
            }
        }

        if (hn) {
            cp_wait1();          // own cp group (kt+1) complete
            convX(kt + 1);       // write buffers[nxt]: safe vs readers via prev barrier
            convW(kt + 1);
            ldgX(kt + 2);
            issueW(kt + 3);
            __syncthreads();     // buffers[nxt] visible for next iteration
        }
    }

    // ---- epilogue: plain stores to this slice's partial buffer ----
    float* up = g_Upart[bz];
    #pragma unroll
    for (int mf = 0; mf < 2; ++mf) {
        int r0 = bm + wm + mf * 16 + g;
        #pragma unroll
        for (int nf = 0; nf < 8; ++nf) {
            int c0 = bn + wn + nf * 8 + q * 2;
            *(float2*)&up[r0 * D_ + c0]       = make_float2(acc[mf][nf][0], acc[mf][nf][1]);
            *(float2*)&up[(r0 + 8) * D_ + c0] = make_float2(acc[mf][nf][2], acc[mf][nf][3]);
        }
    }
}

// ------- per-row cosine (OT via diagonal-IPOT collapse) + split-K reduce -------
__global__ void finalize_kernel(const int* __restrict__ trg, const float* __restrict__ W) {
    int i = blockIdx.x;                  // 512 rows
    int tid = threadIdx.x;               // 128 threads, one float4 (d-chunk) each
    int tg = trg[i];
    int d = tid * 4;
    float4 u = make_float4(0.f, 0.f, 0.f, 0.f);
    #pragma unroll
    for (int s = 0; s < KSL; ++s) {
        float4 p = *(const float4*)&g_Upart[s][i * D_ + d];
        u.x += p.x; u.y += p.y; u.z += p.z; u.w += p.w;
    }
    float4 e = *(const float4*)&W[(size_t)tg * D_ + d];
    float sue = u.x * e.x + u.y * e.y + u.z * e.z + u.w * e.w;
    float suu = u.x * u.x + u.y * u.y + u.z * u.z + u.w * u.w;
    float see = e.x * e.x + e.y * e.y + e.z * e.z + e.w * e.w;
    sue = warp_sum(sue); suu = warp_sum(suu); see = warp_sum(see);
    __shared__ float sm[3][4];
    int warp = tid >> 5, lane = tid & 31;
    if (lane == 0) { sm[0][warp] = sue; sm[1][warp] = suu; sm[2][warp] = see; }
    __syncthreads();
    if (tid == 0) {
        float a = sm[0][0] + sm[0][1] + sm[0][2] + sm[0][3];
        float b = sm[1][0] + sm[1][1] + sm[1][2] + sm[1][3];
        float c = sm[2][0] + sm[2][1] + sm[2][2] + sm[2][3];
        atomicAdd(&g_scal[3], a * rsqrtf(b * c));
    }
}

// ---------------- combine (and reset scalars for the next graph replay) ----------------
__global__ void combine_kernel(const int* __restrict__ dec_len, float* __restrict__ out) {
    int ls = dec_len[0] + dec_len[1] + dec_len[2] + dec_len[3];
    float nll = -g_scal[1] / g_scal[2];
    float cov_loss = g_scal[0] / (float)ls;
    float ot = g_scal[3] / (float)MROWS;
    out[0] = nll + 1.0f * cov_loss + 0.1f + ot;
    #pragma unroll
    for (int i = 0; i < 8; ++i) g_scal[i] = 0.f;
}

extern "C" void kernel_launch(void* const* d_in, const int* in_sizes, int n_in,
                              void* d_out, int out_size) {
    const float* X    = (const float*)d_in[0];
    const float* attn = (const float*)d_in[1];
    const float* covg = (const float*)d_in[2];
    const int*   trg  = (const int*)d_in[3];
    const int*   mask = (const int*)d_in[4];
    const int*   dlen = (const int*)d_in[5];
    const float* W    = (const float*)d_in[6];
    float* out = (float*)d_out;

    cudaFuncSetAttribute(gemm_fused, cudaFuncAttributeMaxDynamicSharedMemorySize,
                         SMEM_BYTES);

    gemm_fused<<<NCTA, NT, SMEM_BYTES>>>(X, W, attn, covg, mask, trg);
    finalize_kernel<<<512, 128>>>(trg, W);
    combine_kernel<<<1, 1>>>(dlen, out);
}

// round 12
// speedup vs baseline: 2.8176x; 1.0484x over previous
#include <cuda_runtime.h>
#include <cuda_bf16.h>
#include <stdint.h>

// Problem constants
#define Bb_  4
#define T_   128
#define V_   50257
#define LSRC 512
#define D_   512
#define MROWS 512              // B*T

// GEMM tiling: 128x256 CTA tile, BK=32, 512 threads, split-K 18
#define BM 128
#define BN 256
#define BK 32
#define NT 512
#define KT2 1571               // ceil(50257/32)
#define KSL 18
#define TPS 88                 // ceil(1571/18)
#define NGEMM 144              // 2 n-blocks * 4 m-blocks * 18 k-slices
#define NCTA 148               // + 4 covnll CTAs = one full wave

#define SAST (128*40)                      // bf16 elems per sA buffer
#define SBST (32*264)                      // bf16 elems per sB buffer
#define OFF_SB (2*SAST*2)                  // 20480
#define SMEM_BYTES (OFF_SB + 2*SBST*2)     // 20480 + 33792 = 54272

__device__ float g_Upart[KSL][MROWS * D_];   // split-K partials (every elem written)
__device__ float g_scal[8];                   // 0:cov 1:nll 2:valid 3:cos (combine resets)

__device__ __forceinline__ float warp_sum(float v) {
    #pragma unroll
    for (int o = 16; o > 0; o >>= 1) v += __shfl_xor_sync(0xffffffffu, v, o);
    return v;
}
__device__ __forceinline__ void ldmatrix_x4(unsigned* r, uint32_t addr) {
    asm volatile("ldmatrix.sync.aligned.m8n8.x4.shared.b16 {%0,%1,%2,%3}, [%4];"
                 : "=r"(r[0]), "=r"(r[1]), "=r"(r[2]), "=r"(r[3]) : "r"(addr));
}
__device__ __forceinline__ void ldmatrix_x4_trans(unsigned* r, uint32_t addr) {
    asm volatile("ldmatrix.sync.aligned.m8n8.x4.trans.shared.b16 {%0,%1,%2,%3}, [%4];"
                 : "=r"(r[0]), "=r"(r[1]), "=r"(r[2]), "=r"(r[3]) : "r"(addr));
}
__device__ __forceinline__ void mma16816(float* c, const unsigned* a, unsigned b0, unsigned b1) {
    asm volatile(
        "mma.sync.aligned.m16n8k16.row.col.f32.bf16.bf16.f32 "
        "{%0,%1,%2,%3}, {%4,%5,%6,%7}, {%8,%9}, {%0,%1,%2,%3};\n"
        : "+f"(c[0]), "+f"(c[1]), "+f"(c[2]), "+f"(c[3])
        : "r"(a[0]), "r"(a[1]), "r"(a[2]), "r"(a[3]), "r"(b0), "r"(b1));
}
__device__ __forceinline__ unsigned packbf(float lo, float hi) {
    __nv_bfloat162 h = __floats2bfloat162_rn(lo, hi);
    return *reinterpret_cast<unsigned*>(&h);
}
// exp of a packed pair via bf16x2 MUFU: exp(x) = 2^(x*log2e)
__device__ __forceinline__ unsigned exp_bf16x2(float x0, float x1) {
    const float L2E = 1.4426950408889634f;
    unsigned p = packbf(x0 * L2E, x1 * L2E);
    unsigned r;
    asm("ex2.approx.ftz.bf16x2 %0, %1;" : "=r"(r) : "r"(p));
    return r;
}

// ======= one-wave kernel: 144 GEMM CTAs + 4 coverage/NLL CTAs =======
__global__ __launch_bounds__(NT, 1) void gemm_fused(
    const float* __restrict__ X, const float* __restrict__ W,
    const float* __restrict__ attn, const float* __restrict__ covg,
    const int* __restrict__ mask, const int* __restrict__ trg)
{
    extern __shared__ char smem[];
    const int id = blockIdx.x;
    const int tid = threadIdx.x;

    if (id >= NGEMM) {
        // ---------- coverage (+ NLL on cid 0) CTA; hides under the GEMM wave ----------
        int* smask = (int*)smem;                 // 512 ints
        float* sred = (float*)(smem + 4096);
        const int cid = id - NGEMM;              // 0..3 == batch index
        smask[tid] = mask[tid];
        __syncthreads();
        float s = 0.f;
        const int* mrow = smask + (cid << 7);
        #pragma unroll 4
        for (int i = 0; i < 32; ++i) {
            int e = (cid << 16) + (i * 512 + tid) * 4;   // elem index, b == cid
            float4 a = *(const float4*)(attn + e);
            float4 c = *(const float4*)(covg + e);
            int t = e & 127;
            if (mrow[t]     == 0) s += fminf(a.x, c.x);
            if (mrow[t + 1] == 0) s += fminf(a.y, c.y);
            if (mrow[t + 2] == 0) s += fminf(a.z, c.z);
            if (mrow[t + 3] == 0) s += fminf(a.w, c.w);
        }
        s = warp_sum(s);
        int warp = tid >> 5, lane = tid & 31;
        if (lane == 0) sred[warp] = s;
        __syncthreads();
        if (tid == 0) {
            float tot = 0.f;
            #pragma unroll
            for (int w = 0; w < 16; ++w) tot += sred[w];
            atomicAdd(&g_scal[0], tot);
        }
        if (cid == 0) {
            // NLL: 512 tokens, one per thread
            float sl = 0.f, cv = 0.f;
            int tg = trg[tid];
            if (tg != 0) {
                sl = logf(X[(size_t)tid * V_ + tg]);
                cv = 1.f;
            }
            sl = warp_sum(sl); cv = warp_sum(cv);
            if (lane == 0) { sred[16 + warp] = sl; sred[32 + warp] = cv; }
            __syncthreads();
            if (tid == 0) {
                float ts = 0.f, tc = 0.f;
                #pragma unroll
                for (int w = 0; w < 16; ++w) { ts += sred[16 + w]; tc += sred[32 + w]; }
                atomicAdd(&g_scal[1], ts);
                atomicAdd(&g_scal[2], tc);
            }
        }
        return;
    }

    // ---------- GEMM CTA: Upart[bz] = exp(X) @ W (k-slice bz) ----------
    __nv_bfloat16* sA = (__nv_bfloat16*)smem;                    // [2][128][40]
    __nv_bfloat16* sB = (__nv_bfloat16*)(smem + OFF_SB);         // [2][32][264] k-major

    const int bz = id >> 3;            // k-slice 0..17
    const int r7 = id & 7;
    const int by = r7 >> 1;            // m-block 0..3
    const int bx = r7 & 1;             // n-block 0..1
    const int bn = bx * BN;
    const int bm = by * BM;
    const int t0 = bz * TPS;
    const int t1 = min(KT2, t0 + TPS);
    const int warp = tid >> 5, lane = tid & 31;
    const int wm = (warp & 3) * 32;      // 4 m-warps
    const int wn = (warp >> 2) * 64;     // 4 n-warps
    const int g = lane >> 2, q = lane & 3;
    const int lm16 = lane & 15, lkh = (lane >> 4) * 8;
    const int bmm = lane >> 3, br = lane & 7;

    const uint32_t sAu = (uint32_t)__cvta_generic_to_shared(sA);
    const uint32_t sBu = (uint32_t)__cvta_generic_to_shared(sB);

    const int xrow = tid >> 2;
    const int xcol = (tid & 3) * 8;

    float acc[2][8][4];
    #pragma unroll
    for (int i = 0; i < 2; i++)
        #pragma unroll
        for (int j = 0; j < 8; j++)
            #pragma unroll
            for (int k = 0; k < 4; k++) acc[i][j][k] = 0.f;

    float xr[8];       // X fp32 staging (one tile ahead)
    unsigned xh[4];    // X bf16x2 (exp applied)
    float wf[16];      // W fp32 staging (one tile ahead)

    auto ldgX = [&](int kt) {
        if (kt >= t1) return;
        const int k0 = kt * BK;
        const float* p = X + (size_t)(bm + xrow) * V_ + k0 + xcol;
        if (k0 + BK <= V_) {
            #pragma unroll
            for (int j = 0; j < 8; ++j) xr[j] = __ldg(p + j);
        } else {
            #pragma unroll
            for (int j = 0; j < 8; ++j)
                xr[j] = (k0 + xcol + j < V_) ? __ldg(p + j) : 0.f;
        }
    };
    auto ldgW = [&](int kt) {
        if (kt >= t1) return;
        const int k0 = kt * BK;
        if (k0 + BK <= V_) {
            #pragma unroll
            for (int i = 0; i < 4; ++i) {
                int c = tid + i * NT;
                int k = c >> 6, n4 = (c & 63) * 4;
                *(float4*)&wf[i * 4] =
                    *(const float4*)(W + (size_t)(k0 + k) * D_ + bn + n4);
            }
        } else {
            #pragma unroll
            for (int i = 0; i < 4; ++i) {
                int c = tid + i * NT;
                int k = c >> 6, n4 = (c & 63) * 4;
                float4 v = make_float4(0.f, 0.f, 0.f, 0.f);
                if (k0 + k < V_)
                    v = *(const float4*)(W + (size_t)(k0 + k) * D_ + bn + n4);
                *(float4*)&wf[i * 4] = v;
            }
        }
    };
    auto expX = [&]() {
        #pragma unroll
        for (int j = 0; j < 4; ++j)
            xh[j] = exp_bf16x2(xr[2 * j], xr[2 * j + 1]);
    };
    auto convX = [&](int kt) {   // xh -> sA[kt&1]
        __nv_bfloat16* dstA = sA + (kt & 1) * SAST;
        *(uint4*)&dstA[xrow * 40 + xcol] = *(uint4*)xh;
    };
    auto convW = [&](int kt) {   // wf regs -> bf16 -> sB[kt&1]
        __nv_bfloat16* dstB = sB + (kt & 1) * SBST;
        #pragma unroll
        for (int i = 0; i < 4; ++i) {
            int c = tid + i * NT;
            int k = c >> 6, n4 = (c & 63) * 4;
            float4 v = *(const float4*)&wf[i * 4];
            *(uint2*)&dstB[k * 264 + n4] =
                make_uint2(packbf(v.x, v.y), packbf(v.z, v.w));
        }
    };

    // ---- prologue: tile t0 -> smem; prefetch t0+1 into regs ----
    ldgX(t0);
    ldgW(t0);
    expX();
    convX(t0);
    convW(t0);
    ldgX(t0 + 1);
    ldgW(t0 + 1);
    __syncthreads();        // buffers (t0&1) visible to all

    for (int kt = t0; kt < t1; ++kt) {
        const int cur = kt & 1;
        const bool hn = (kt + 1 < t1);

        if (hn) expX();     // exp of X(kt+1); LDG latency covered by prev iteration

        // ---- mma on buffers[cur] ----
        const uint32_t sAc = sAu + (uint32_t)(cur * SAST * 2);
        const uint32_t sBc = sBu + (uint32_t)(cur * SBST * 2);
        #pragma unroll
        for (int kk = 0; kk < 2; ++kk) {
            unsigned a0[2][4];
            #pragma unroll
            for (int mf = 0; mf < 2; ++mf) {
                uint32_t addr = sAc +
                    (uint32_t)(((wm + mf * 16 + lm16) * 40 + kk * 16 + lkh) * 2);
                ldmatrix_x4(a0[mf], addr);
            }
            #pragma unroll
            for (int p = 0; p < 4; ++p) {
                unsigned bfr[4];
                int ksrc = kk * 16 + (bmm & 1) * 8 + br;
                int nsrc = wn + p * 16 + (bmm >> 1) * 8;
                ldmatrix_x4_trans(bfr, sBc + (uint32_t)((ksrc * 264 + nsrc) * 2));
                #pragma unroll
                for (int mf = 0; mf < 2; ++mf) {
                    mma16816(acc[mf][2 * p],     a0[mf], bfr[0], bfr[1]);
                    mma16816(acc[mf][2 * p + 1], a0[mf], bfr[2], bfr[3]);
                }
            }
        }

        if (hn) {
            convX(kt + 1);       // write buffers[nxt]: safe vs readers via prev barrier
            convW(kt + 1);
            ldgX(kt + 2);        // refill reg stages
            ldgW(kt + 2);
            __syncthreads();     // buffers[nxt] visible for next iteration
        }
    }

    // ---- epilogue: plain stores to this slice's partial buffer ----
    float* up = g_Upart[bz];
    #pragma unroll
    for (int mf = 0; mf < 2; ++mf) {
        int r0 = bm + wm + mf * 16 + g;
        #pragma unroll
        for (int nf = 0; nf < 8; ++nf) {
            int c0 = bn + wn + nf * 8 + q * 2;
            *(float2*)&up[r0 * D_ + c0]       = make_float2(acc[mf][nf][0], acc[mf][nf][1]);
            *(float2*)&up[(r0 + 8) * D_ + c0] = make_float2(acc[mf][nf][2], acc[mf][nf][3]);
        }
    }
}

// ------- per-row cosine (OT via diagonal-IPOT collapse) + split-K reduce -------
__global__ void finalize_kernel(const int* __restrict__ trg, const float* __restrict__ W) {
    int i = blockIdx.x;                  // 512 rows
    int tid = threadIdx.x;               // 128 threads, one float4 (d-chunk) each
    int tg = trg[i];
    int d = tid * 4;
    float4 u = make_float4(0.f, 0.f, 0.f, 0.f);
    #pragma unroll
    for (int s = 0; s < KSL; ++s) {
        float4 p = *(const float4*)&g_Upart[s][i * D_ + d];
        u.x += p.x; u.y += p.y; u.z += p.z; u.w += p.w;
    }
    float4 e = *(const float4*)&W[(size_t)tg * D_ + d];
    float sue = u.x * e.x + u.y * e.y + u.z * e.z + u.w * e.w;
    float suu = u.x * u.x + u.y * u.y + u.z * u.z + u.w * u.w;
    float see = e.x * e.x + e.y * e.y + e.z * e.z + e.w * e.w;
    sue = warp_sum(sue); suu = warp_sum(suu); see = warp_sum(see);
    __shared__ float sm[3][4];
    int warp = tid >> 5, lane = tid & 31;
    if (lane == 0) { sm[0][warp] = sue; sm[1][warp] = suu; sm[2][warp] = see; }
    __syncthreads();
    if (tid == 0) {
        float a = sm[0][0] + sm[0][1] + sm[0][2] + sm[0][3];
        float b = sm[1][0] + sm[1][1] + sm[1][2] + sm[1][3];
        float c = sm[2][0] + sm[2][1] + sm[2][2] + sm[2][3];
        atomicAdd(&g_scal[3], a * rsqrtf(b * c));
    }
}

// ---------------- combine (and reset scalars for the next graph replay) ----------------
__global__ void combine_kernel(const int* __restrict__ dec_len, float* __restrict__ out) {
    int ls = dec_len[0] + dec_len[1] + dec_len[2] + dec_len[3];
    float nll = -g_scal[1] / g_scal[2];
    float cov_loss = g_scal[0] / (float)ls;
    float ot = g_scal[3] / (float)MROWS;
    out[0] = nll + 1.0f * cov_loss + 0.1f + ot;
    #pragma unroll
    for (int i = 0; i < 8; ++i) g_scal[i] = 0.f;
}

extern "C" void kernel_launch(void* const* d_in, const int* in_sizes, int n_in,
                              void* d_out, int out_size) {
    const float* X    = (const float*)d_in[0];
    const float* attn = (const float*)d_in[1];
    const float* covg = (const float*)d_in[2];
    const int*   trg  = (const int*)d_in[3];
    const int*   mask = (const int*)d_in[4];
    const int*   dlen = (const int*)d_in[5];
    const float* W    = (const float*)d_in[6];
    float* out = (float*)d_out;

    cudaFuncSetAttribute(gemm_fused, cudaFuncAttributeMaxDynamicSharedMemorySize,
                         SMEM_BYTES);

    gemm_fused<<<NCTA, NT, SMEM_BYTES>>>(X, W, attn, covg, mask, trg);
    finalize_kernel<<<512, 128>>>(trg, W);
    combine_kernel<<<1, 1>>>(dlen, out);
}

// round 13
// speedup vs baseline: 3.0280x; 1.0747x over previous
#include <cuda_runtime.h>
#include <cuda_bf16.h>
#include <stdint.h>

// Problem constants
#define Bb_  4
#define T_   128
#define V_   50257
#define LSRC 512
#define D_   512
#define MROWS 512              // B*T

// GEMM tiling: 128x256 CTA tile, BK=32, 512 threads, split-K 18
#define BM 128
#define BN 256
#define BK 32
#define NT 512
#define KT2 1571               // ceil(50257/32)
#define KSL 18
#define TPS 88                 // ceil(1571/18)
#define NGEMM 144              // 2 n-blocks * 4 m-blocks * 18 k-slices
#define NCTA 148               // + 4 covnll CTAs = one full wave

#define SAST (128*40)                      // bf16 elems per sA buffer
#define SBST (32*264)                      // bf16 elems per sB buffer
#define OFF_SB (2*SAST*2)                  // 20480
#define SMEM_BYTES (OFF_SB + 2*SBST*2)     // 20480 + 33792 = 54272

__device__ float g_Upart[KSL][MROWS * D_];   // split-K partials (every elem written)
__device__ float g_scal[8];                   // 0:cov 1:nll 2:valid 3:cos (combine resets)

__device__ __forceinline__ float warp_sum(float v) {
    #pragma unroll
    for (int o = 16; o > 0; o >>= 1) v += __shfl_xor_sync(0xffffffffu, v, o);
    return v;
}
__device__ __forceinline__ void ldmatrix_x4(unsigned* r, uint32_t addr) {
    asm volatile("ldmatrix.sync.aligned.m8n8.x4.shared.b16 {%0,%1,%2,%3}, [%4];"
                 : "=r"(r[0]), "=r"(r[1]), "=r"(r[2]), "=r"(r[3]) : "r"(addr));
}
__device__ __forceinline__ void ldmatrix_x4_trans(unsigned* r, uint32_t addr) {
    asm volatile("ldmatrix.sync.aligned.m8n8.x4.trans.shared.b16 {%0,%1,%2,%3}, [%4];"
                 : "=r"(r[0]), "=r"(r[1]), "=r"(r[2]), "=r"(r[3]) : "r"(addr));
}
__device__ __forceinline__ void mma16816(float* c, const unsigned* a, unsigned b0, unsigned b1) {
    asm volatile(
        "mma.sync.aligned.m16n8k16.row.col.f32.bf16.bf16.f32 "
        "{%0,%1,%2,%3}, {%4,%5,%6,%7}, {%8,%9}, {%0,%1,%2,%3};\n"
        : "+f"(c[0]), "+f"(c[1]), "+f"(c[2]), "+f"(c[3])
        : "r"(a[0]), "r"(a[1]), "r"(a[2]), "r"(a[3]), "r"(b0), "r"(b1));
}
__device__ __forceinline__ unsigned packbf(float lo, float hi) {
    __nv_bfloat162 h = __floats2bfloat162_rn(lo, hi);
    return *reinterpret_cast<unsigned*>(&h);
}
// exp of a packed pair via bf16x2 MUFU: exp(x) = 2^(x*log2e)
__device__ __forceinline__ unsigned exp_bf16x2(float x0, float x1) {
    const float L2E = 1.4426950408889634f;
    unsigned p = packbf(x0 * L2E, x1 * L2E);
    unsigned r;
    asm("ex2.approx.ftz.bf16x2 %0, %1;" : "=r"(r) : "r"(p));
    return r;
}

// ======= one-wave kernel: 144 GEMM CTAs + 4 coverage/NLL CTAs =======
__global__ __launch_bounds__(NT, 1) void gemm_fused(
    const float* __restrict__ X, const float* __restrict__ W,
    const float* __restrict__ attn, const float* __restrict__ covg,
    const int* __restrict__ mask, const int* __restrict__ trg)
{
    extern __shared__ char smem[];
    const int id = blockIdx.x;
    const int tid = threadIdx.x;

    if (id >= NGEMM) {
        // ---------- coverage (+ NLL on cid 0) CTA; hides under the GEMM wave ----------
        int* smask = (int*)smem;                 // 512 ints
        float* sred = (float*)(smem + 4096);
        const int cid = id - NGEMM;              // 0..3 == batch index
        smask[tid] = mask[tid];
        __syncthreads();
        float s = 0.f;
        const int* mrow = smask + (cid << 7);
        #pragma unroll 4
        for (int i = 0; i < 32; ++i) {
            int e = (cid << 16) + (i * 512 + tid) * 4;   // elem index, b == cid
            float4 a = *(const float4*)(attn + e);
            float4 c = *(const float4*)(covg + e);
            int t = e & 127;
            if (mrow[t]     == 0) s += fminf(a.x, c.x);
            if (mrow[t + 1] == 0) s += fminf(a.y, c.y);
            if (mrow[t + 2] == 0) s += fminf(a.z, c.z);
            if (mrow[t + 3] == 0) s += fminf(a.w, c.w);
        }
        s = warp_sum(s);
        int warp = tid >> 5, lane = tid & 31;
        if (lane == 0) sred[warp] = s;
        __syncthreads();
        if (tid == 0) {
            float tot = 0.f;
            #pragma unroll
            for (int w = 0; w < 16; ++w) tot += sred[w];
            atomicAdd(&g_scal[0], tot);
        }
        if (cid == 0) {
            // NLL: 512 tokens, one per thread
            float sl = 0.f, cv = 0.f;
            int tg = trg[tid];
            if (tg != 0) {
                sl = logf(X[(size_t)tid * V_ + tg]);
                cv = 1.f;
            }
            sl = warp_sum(sl); cv = warp_sum(cv);
            if (lane == 0) { sred[16 + warp] = sl; sred[32 + warp] = cv; }
            __syncthreads();
            if (tid == 0) {
                float ts = 0.f, tc = 0.f;
                #pragma unroll
                for (int w = 0; w < 16; ++w) { ts += sred[16 + w]; tc += sred[32 + w]; }
                atomicAdd(&g_scal[1], ts);
                atomicAdd(&g_scal[2], tc);
            }
        }
        return;
    }

    // ---------- GEMM CTA: Upart[bz] = exp(X) @ W (k-slice bz) ----------
    __nv_bfloat16* sA = (__nv_bfloat16*)smem;                    // [2][128][40]
    __nv_bfloat16* sB = (__nv_bfloat16*)(smem + OFF_SB);         // [2][32][264] k-major

    const int bz = id >> 3;            // k-slice 0..17
    const int r7 = id & 7;
    const int by = r7 >> 1;            // m-block 0..3
    const int bx = r7 & 1;             // n-block 0..1
    const int bn = bx * BN;
    const int bm = by * BM;
    const int t0 = bz * TPS;
    const int t1 = min(KT2, t0 + TPS);
    const int warp = tid >> 5, lane = tid & 31;
    const int wm = (warp & 3) * 32;      // 4 m-warps
    const int wn = (warp >> 2) * 64;     // 4 n-warps
    const int g = lane >> 2, q = lane & 3;
    const int lm16 = lane & 15, lkh = (lane >> 4) * 8;
    const int bmm = lane >> 3, br = lane & 7;

    const uint32_t sAu = (uint32_t)__cvta_generic_to_shared(sA);
    const uint32_t sBu = (uint32_t)__cvta_generic_to_shared(sB);

    // X mapping (coalesced): column = lane, rows = warp + 16*i  (i = 0..7)
    const int xc = lane;               // k-column within tile
    const int xb = warp;               // base row (0..15)

    float acc[2][8][4];
    #pragma unroll
    for (int i = 0; i < 2; i++)
        #pragma unroll
        for (int j = 0; j < 8; j++)
            #pragma unroll
            for (int k = 0; k < 4; k++) acc[i][j][k] = 0.f;

    float xr[8];       // X fp32 staging (one tile ahead), rows xb+16i
    unsigned xh[4];    // X bf16x2 (exp applied), pairs (i=2j, i=2j+1)
    float wf[16];      // W fp32 staging (one tile ahead)

    auto ldgX = [&](int kt) {
        if (kt >= t1) return;
        const int k0 = kt * BK;
        const float* p = X + (size_t)(bm + xb) * V_ + k0 + xc;
        if (k0 + BK <= V_) {
            #pragma unroll
            for (int i = 0; i < 8; ++i) { xr[i] = __ldg(p); p += (size_t)16 * V_; }
        } else {
            const bool ok = (k0 + xc) < V_;
            #pragma unroll
            for (int i = 0; i < 8; ++i) { xr[i] = ok ? __ldg(p) : 0.f; p += (size_t)16 * V_; }
        }
    };
    auto ldgW = [&](int kt) {
        if (kt >= t1) return;
        const int k0 = kt * BK;
        if (k0 + BK <= V_) {
            #pragma unroll
            for (int i = 0; i < 4; ++i) {
                int c = tid + i * NT;
                int k = c >> 6, n4 = (c & 63) * 4;
                *(float4*)&wf[i * 4] =
                    *(const float4*)(W + (size_t)(k0 + k) * D_ + bn + n4);
            }
        } else {
            #pragma unroll
            for (int i = 0; i < 4; ++i) {
                int c = tid + i * NT;
                int k = c >> 6, n4 = (c & 63) * 4;
                float4 v = make_float4(0.f, 0.f, 0.f, 0.f);
                if (k0 + k < V_)
                    v = *(const float4*)(W + (size_t)(k0 + k) * D_ + bn + n4);
                *(float4*)&wf[i * 4] = v;
            }
        }
    };
    auto expX = [&]() {
        #pragma unroll
        for (int j = 0; j < 4; ++j)
            xh[j] = exp_bf16x2(xr[2 * j], xr[2 * j + 1]);
    };
    auto convX = [&](int kt) {   // xh -> sA[kt&1]; rows xb+32j (low) and xb+32j+16 (high)
        __nv_bfloat16* dstA = sA + (kt & 1) * SAST;
        #pragma unroll
        for (int j = 0; j < 4; ++j) {
            __nv_bfloat162 h = *reinterpret_cast<__nv_bfloat162*>(&xh[j]);
            dstA[(xb + 32 * j) * 40 + xc]      = __low2bfloat16(h);
            dstA[(xb + 32 * j + 16) * 40 + xc] = __high2bfloat16(h);
        }
    };
    auto convW = [&](int kt) {   // wf regs -> bf16 -> sB[kt&1]
        __nv_bfloat16* dstB = sB + (kt & 1) * SBST;
        #pragma unroll
        for (int i = 0; i < 4; ++i) {
            int c = tid + i * NT;
            int k = c >> 6, n4 = (c & 63) * 4;
            float4 v = *(const float4*)&wf[i * 4];
            *(uint2*)&dstB[k * 264 + n4] =
                make_uint2(packbf(v.x, v.y), packbf(v.z, v.w));
        }
    };

    // ---- prologue: tile t0 -> smem; prefetch t0+1 into regs ----
    ldgX(t0);
    ldgW(t0);
    expX();
    convX(t0);
    convW(t0);
    ldgX(t0 + 1);
    ldgW(t0 + 1);
    __syncthreads();        // buffers (t0&1) visible to all

    for (int kt = t0; kt < t1; ++kt) {
        const int cur = kt & 1;
        const bool hn = (kt + 1 < t1);

        if (hn) expX();     // exp of X(kt+1); LDG latency covered by prev iteration

        // ---- mma on buffers[cur] ----
        const uint32_t sAc = sAu + (uint32_t)(cur * SAST * 2);
        const uint32_t sBc = sBu + (uint32_t)(cur * SBST * 2);
        #pragma unroll
        for (int kk = 0; kk < 2; ++kk) {
            unsigned a0[2][4];
            #pragma unroll
            for (int mf = 0; mf < 2; ++mf) {
                uint32_t addr = sAc +
                    (uint32_t)(((wm + mf * 16 + lm16) * 40 + kk * 16 + lkh) * 2);
                ldmatrix_x4(a0[mf], addr);
            }
            #pragma unroll
            for (int p = 0; p < 4; ++p) {
                unsigned bfr[4];
                int ksrc = kk * 16 + (bmm & 1) * 8 + br;
                int nsrc = wn + p * 16 + (bmm >> 1) * 8;
                ldmatrix_x4_trans(bfr, sBc + (uint32_t)((ksrc * 264 + nsrc) * 2));
                #pragma unroll
                for (int mf = 0; mf < 2; ++mf) {
                    mma16816(acc[mf][2 * p],     a0[mf], bfr[0], bfr[1]);
                    mma16816(acc[mf][2 * p + 1], a0[mf], bfr[2], bfr[3]);
                }
            }
        }

        if (hn) {
            convX(kt + 1);       // write buffers[nxt]: safe vs readers via prev barrier
            convW(kt + 1);
            ldgX(kt + 2);        // refill reg stages
            ldgW(kt + 2);
            __syncthreads();     // buffers[nxt] visible for next iteration
        }
    }

    // ---- epilogue: plain stores to this slice's partial buffer ----
    float* up = g_Upart[bz];
    #pragma unroll
    for (int mf = 0; mf < 2; ++mf) {
        int r0 = bm + wm + mf * 16 + g;
        #pragma unroll
        for (int nf = 0; nf < 8; ++nf) {
            int c0 = bn + wn + nf * 8 + q * 2;
            *(float2*)&up[r0 * D_ + c0]       = make_float2(acc[mf][nf][0], acc[mf][nf][1]);
            *(float2*)&up[(r0 + 8) * D_ + c0] = make_float2(acc[mf][nf][2], acc[mf][nf][3]);
        }
    }
}

// ------- per-row cosine (OT via diagonal-IPOT collapse) + split-K reduce -------
__global__ void finalize_kernel(const int* __restrict__ trg, const float* __restrict__ W) {
    int i = blockIdx.x;                  // 512 rows
    int tid = threadIdx.x;               // 128 threads, one float4 (d-chunk) each
    int tg = trg[i];
    int d = tid * 4;
    float4 u = make_float4(0.f, 0.f, 0.f, 0.f);
    #pragma unroll
    for (int s = 0; s < KSL; ++s) {
        float4 p = *(const float4*)&g_Upart[s][i * D_ + d];
        u.x += p.x; u.y += p.y; u.z += p.z; u.w += p.w;
    }
    float4 e = *(const float4*)&W[(size_t)tg * D_ + d];
    float sue = u.x * e.x + u.y * e.y + u.z * e.z + u.w * e.w;
    float suu = u.x * u.x + u.y * u.y + u.z * u.z + u.w * u.w;
    float see = e.x * e.x + e.y * e.y + e.z * e.z + e.w * e.w;
    sue = warp_sum(sue); suu = warp_sum(suu); see = warp_sum(see);
    __shared__ float sm[3][4];
    int warp = tid >> 5, lane = tid & 31;
    if (lane == 0) { sm[0][warp] = sue; sm[1][warp] = suu; sm[2][warp] = see; }
    __syncthreads();
    if (tid == 0) {
        float a = sm[0][0] + sm[0][1] + sm[0][2] + sm[0][3];
        float b = sm[1][0] + sm[1][1] + sm[1][2] + sm[1][3];
        float c = sm[2][0] + sm[2][1] + sm[2][2] + sm[2][3];
        atomicAdd(&g_scal[3], a * rsqrtf(b * c));
    }
}

// ---------------- combine (and reset scalars for the next graph replay) ----------------
__global__ void combine_kernel(const int* __restrict__ dec_len, float* __restrict__ out) {
    int ls = dec_len[0] + dec_len[1] + dec_len[2] + dec_len[3];
    float nll = -g_scal[1] / g_scal[2];
    float cov_loss = g_scal[0] / (float)ls;
    float ot = g_scal[3] / (float)MROWS;
    out[0] = nll + 1.0f * cov_loss + 0.1f + ot;
    #pragma unroll
    for (int i = 0; i < 8; ++i) g_scal[i] = 0.f;
}

extern "C" void kernel_launch(void* const* d_in, const int* in_sizes, int n_in,
                              void* d_out, int out_size) {
    const float* X    = (const float*)d_in[0];
    const float* attn = (const float*)d_in[1];
    const float* covg = (const float*)d_in[2];
    const int*   trg  = (const int*)d_in[3];
    const int*   mask = (const int*)d_in[4];
    const int*   dlen = (const int*)d_in[5];
    const float* W    = (const float*)d_in[6];
    float* out = (float*)d_out;

    cudaFuncSetAttribute(gemm_fused, cudaFuncAttributeMaxDynamicSharedMemorySize,
                         SMEM_BYTES);

    gemm_fused<<<NCTA, NT, SMEM_BYTES>>>(X, W, attn, covg, mask, trg);
    finalize_kernel<<<512, 128>>>(trg, W);
    combine_kernel<<<1, 1>>>(dlen, out);
}